// round 1
// baseline (speedup 1.0000x reference)
#include <cuda_runtime.h>

// MMDLoss: hard-negative selection (argmax over 4x4 upsample candidates) + RBF MMD.
// x: (2,768,32,32) f32, y: (2,768,128,128) f32, output: scalar f32.

#define GAMMA_F 0.00065f

constexpr int C_  = 768;
constexpr int N_  = 2048;   // B*H1*W1 = 2*32*32
constexpr int NZ  = 4096;   // X rows + Ysel rows
constexpr int K_  = 768;

// Scratch (static device globals; no allocation allowed)
__device__ float  g_Z[NZ * K_];          // rows 0..2047 = X, 2048..4095 = Ysel
__device__ float  g_sq[NZ];              // row squared norms
__device__ float  g_D2P[N_ * 16 * 4];    // partial d2 sums (4 c-chunks)
__device__ int    g_idx[N_];
__device__ double g_acc[3];              // 0=xx (strict lower), 1=xy (full), 2=yy (strict lower)

// ---------------------------------------------------------------------------
// 1) Build X rows of Z:  Z[n][c] = x[b][c][h1][w1],  n = (b*32+h1)*32+w1
// ---------------------------------------------------------------------------
__global__ void build_x_kernel(const float* __restrict__ x) {
  int n = blockIdx.x;
  int b = n >> 10, h1 = (n >> 5) & 31, w1 = n & 31;
  int base = (b * C_) * 1024 + h1 * 32 + w1;
#pragma unroll
  for (int k = 0; k < 3; ++k) {
    int c = threadIdx.x + 256 * k;
    g_Z[n * K_ + c] = x[base + c * 1024];
  }
}

// ---------------------------------------------------------------------------
// 2) Partial squared distances: block = (b, h1, r, c-chunk), thread = (w1, s)
//    Coalesced y reads (128 contiguous floats per c per block).
// ---------------------------------------------------------------------------
__global__ void d2_kernel(const float* __restrict__ y) {
  int chunk = blockIdx.x & 3;
  int r  = (blockIdx.x >> 2) & 3;
  int h1 = (blockIdx.x >> 4) & 31;
  int b  = blockIdx.x >> 9;
  int t  = threadIdx.x;          // 0..127 == w1*4 + s
  int w1 = t >> 2;
  int n  = (b * 32 + h1) * 32 + w1;
  int c0 = chunk * 192;
  const float* yp = y + (size_t)(b * C_ + c0) * 16384 + (h1 * 4 + r) * 128 + t;
  const float* zp = g_Z + (size_t)n * K_ + c0;
  float a0 = 0.f, a1 = 0.f;
#pragma unroll 8
  for (int c = 0; c < 192; c += 2) {
    float d0 = zp[c]     - yp[(size_t)c * 16384];
    float d1 = zp[c + 1] - yp[(size_t)(c + 1) * 16384];
    a0 = fmaf(d0, d0, a0);
    a1 = fmaf(d1, d1, a1);
  }
  g_D2P[(n * 16 + (r * 4 + (t & 3))) * 4 + chunk] = a0 + a1;
}

// ---------------------------------------------------------------------------
// 3) Argmax over the 16 candidates per point (first-max tie rule, matches jnp)
// ---------------------------------------------------------------------------
__global__ void argmax_kernel() {
  int n = blockIdx.x * blockDim.x + threadIdx.x;
  if (n >= N_) return;
  const float* p = g_D2P + n * 64;
  float best = -1.f; int bi = 0;
#pragma unroll
  for (int j = 0; j < 16; ++j) {
    float d = (p[j * 4] + p[j * 4 + 1]) + (p[j * 4 + 2] + p[j * 4 + 3]);
    if (d > best) { best = d; bi = j; }
  }
  g_idx[n] = bi;
}

// ---------------------------------------------------------------------------
// 4) Gather selected y rows into Z[2048..4095]
// ---------------------------------------------------------------------------
__global__ void gather_kernel(const float* __restrict__ y) {
  int n = blockIdx.x;
  int b = n >> 10, h1 = (n >> 5) & 31, w1 = n & 31;
  int j = g_idx[n];
  int h = h1 * 4 + (j >> 2), w = w1 * 4 + (j & 3);
  size_t base = (size_t)(b * C_) * 16384 + (size_t)h * 128 + w;
#pragma unroll
  for (int k = 0; k < 3; ++k) {
    int c = threadIdx.x + 256 * k;
    g_Z[(size_t)(N_ + n) * K_ + c] = y[base + (size_t)c * 16384];
  }
}

// ---------------------------------------------------------------------------
// 5) Row squared norms of Z
// ---------------------------------------------------------------------------
__global__ void sqnorm_kernel() {
  int i = blockIdx.x;
  const float* row = g_Z + (size_t)i * K_;
  float s = 0.f;
#pragma unroll
  for (int k = 0; k < 3; ++k) {
    float v = row[threadIdx.x + 256 * k];
    s = fmaf(v, v, s);
  }
  for (int off = 16; off; off >>= 1) s += __shfl_down_sync(0xffffffffu, s, off);
  __shared__ float red[8];
  int lane = threadIdx.x & 31, wid = threadIdx.x >> 5;
  if (lane == 0) red[wid] = s;
  __syncthreads();
  if (threadIdx.x == 0) {
    float t = 0.f;
#pragma unroll
    for (int w = 0; w < 8; ++w) t += red[w];
    g_sq[i] = t;
  }
}

__global__ void zero_kernel() {
  if (threadIdx.x < 3) g_acc[threadIdx.x] = 0.0;
}

// ---------------------------------------------------------------------------
// 6) Symmetric gram over Z (lower triangle only) with packed f32x2 FMA.
//    128x128 block tile, BK=8, 8x8 per thread (as 4 m-pairs x 8 n), fused
//    exp(-gamma*dist) epilogue + per-class accumulation.
// ---------------------------------------------------------------------------
__device__ __forceinline__ void ffma2(unsigned long long& c,
                                      unsigned long long a,
                                      unsigned long long b) {
  asm("fma.rn.f32x2 %0, %1, %2, %0;" : "+l"(c) : "l"(a), "l"(b));
}
__device__ __forceinline__ unsigned long long pack2(float v) {
  unsigned long long r;
  asm("mov.b64 %0, {%1, %2};" : "=l"(r) : "f"(v), "f"(v));
  return r;
}

__global__ void __launch_bounds__(256, 2) gram_kernel() {
  __shared__ float As[2][8][128];
  __shared__ float Bs[2][8][128];
  __shared__ float red[8];

  int bid = blockIdx.x;
  // bid -> (br, bc), bc <= br, over 32x32 tiles
  int br = (int)((sqrtf(8.f * (float)bid + 1.f) - 1.f) * 0.5f);
  while ((br + 1) * (br + 2) / 2 <= bid) br++;
  while (br * (br + 1) / 2 > bid) br--;
  int bc = bid - br * (br + 1) / 2;

  int i0 = br * 128, j0 = bc * 128;
  int tid = threadIdx.x;
  int tx = tid & 15, ty = tid >> 4;

  // global-load mapping: 256 threads * 1 float4 = 1024 floats = 128 rows x 8 k
  int lrow = tid >> 1;
  int lk   = (tid & 1) * 4;
  const float* gA = g_Z + (size_t)(i0 + lrow) * K_ + lk;
  const float* gB = g_Z + (size_t)(j0 + lrow) * K_ + lk;

  unsigned long long acc2[4][8];
#pragma unroll
  for (int mp = 0; mp < 4; ++mp)
#pragma unroll
    for (int nn = 0; nn < 8; ++nn) acc2[mp][nn] = 0ull;

  float4 an = *(const float4*)gA;
  float4 bn = *(const float4*)gB;

  As[0][lk + 0][lrow] = an.x; As[0][lk + 1][lrow] = an.y;
  As[0][lk + 2][lrow] = an.z; As[0][lk + 3][lrow] = an.w;
  Bs[0][lk + 0][lrow] = bn.x; Bs[0][lk + 1][lrow] = bn.y;
  Bs[0][lk + 2][lrow] = bn.z; Bs[0][lk + 3][lrow] = bn.w;
  __syncthreads();

  int buf = 0;
  for (int kt = 0; kt < 96; ++kt) {
    if (kt + 1 < 96) {
      an = *(const float4*)(gA + (kt + 1) * 8);
      bn = *(const float4*)(gB + (kt + 1) * 8);
    }
#pragma unroll
    for (int kk = 0; kk < 8; ++kk) {
      // A pairs come out of SMEM already packed as b64 (no MOVs)
      ulonglong2 apA = *(const ulonglong2*)&As[buf][kk][ty * 8];
      float4 bv0 = *(const float4*)&Bs[buf][kk][tx * 8];
      float4 bv1 = *(const float4*)&Bs[buf][kk][tx * 8 + 4];
      unsigned long long aa0 = apA.x, aa1 = apA.y;
      ulonglong2 apB = *(const ulonglong2*)&As[buf][kk][ty * 8 + 4];
      unsigned long long aa2 = apB.x, aa3 = apB.y;
      unsigned long long bb[8] = {
        pack2(bv0.x), pack2(bv0.y), pack2(bv0.z), pack2(bv0.w),
        pack2(bv1.x), pack2(bv1.y), pack2(bv1.z), pack2(bv1.w)
      };
#pragma unroll
      for (int nn = 0; nn < 8; ++nn) {
        ffma2(acc2[0][nn], aa0, bb[nn]);
        ffma2(acc2[1][nn], aa1, bb[nn]);
        ffma2(acc2[2][nn], aa2, bb[nn]);
        ffma2(acc2[3][nn], aa3, bb[nn]);
      }
    }
    if (kt + 1 < 96) {
      int nb = buf ^ 1;
      As[nb][lk + 0][lrow] = an.x; As[nb][lk + 1][lrow] = an.y;
      As[nb][lk + 2][lrow] = an.z; As[nb][lk + 3][lrow] = an.w;
      Bs[nb][lk + 0][lrow] = bn.x; Bs[nb][lk + 1][lrow] = bn.y;
      Bs[nb][lk + 2][lrow] = bn.z; Bs[nb][lk + 3][lrow] = bn.w;
    }
    __syncthreads();
    buf ^= 1;
  }

  // Epilogue: kernel values + masked accumulation
  int  cls  = (br < 16) ? 0 : ((bc < 16) ? 1 : 2);
  bool diag = (br == bc);
  int  im0 = i0 + ty * 8, jn0 = j0 + tx * 8;
  float sqi[8], sqj[8];
#pragma unroll
  for (int q = 0; q < 8; ++q) { sqi[q] = g_sq[im0 + q]; sqj[q] = g_sq[jn0 + q]; }

  float lsum = 0.f;
#pragma unroll
  for (int mp = 0; mp < 4; ++mp) {
#pragma unroll
    for (int nn = 0; nn < 8; ++nn) {
      float2 cv = *(float2*)&acc2[mp][nn];
      int m0 = 2 * mp, m1 = 2 * mp + 1;
      float d0 = fmaxf(sqi[m0] + sqj[nn] - 2.f * cv.x, 0.f);
      float d1 = fmaxf(sqi[m1] + sqj[nn] - 2.f * cv.y, 0.f);
      float e0 = __expf(-GAMMA_F * d0);
      float e1 = __expf(-GAMMA_F * d1);
      if (!diag || (tx * 8 + nn) < (ty * 8 + m0)) lsum += e0;
      if (!diag || (tx * 8 + nn) < (ty * 8 + m1)) lsum += e1;
    }
  }

  for (int off = 16; off; off >>= 1) lsum += __shfl_down_sync(0xffffffffu, lsum, off);
  if ((tid & 31) == 0) red[tid >> 5] = lsum;
  __syncthreads();
  if (tid == 0) {
    float s = 0.f;
#pragma unroll
    for (int w = 0; w < 8; ++w) s += red[w];
    atomicAdd(&g_acc[cls], (double)s);
  }
}

// ---------------------------------------------------------------------------
// 7) Final combine: symmetric halves doubled, exact diagonal (exp(0)=1) added
// ---------------------------------------------------------------------------
__global__ void finalize_kernel(float* out) {
  double sxx = 2.0 * g_acc[0] + (double)N_;
  double syy = 2.0 * g_acc[2] + (double)N_;
  double sxy = g_acc[1];
  out[0] = (float)((sxx + syy - 2.0 * sxy) / ((double)N_ * (double)N_));
}

extern "C" void kernel_launch(void* const* d_in, const int* in_sizes, int n_in,
                              void* d_out, int out_size) {
  const float* x = (const float*)d_in[0];
  const float* y = (const float*)d_in[1];

  build_x_kernel<<<2048, 256>>>(x);
  d2_kernel<<<1024, 128>>>(y);
  argmax_kernel<<<8, 256>>>();
  gather_kernel<<<2048, 256>>>(y);
  sqnorm_kernel<<<4096, 256>>>();
  zero_kernel<<<1, 32>>>();
  gram_kernel<<<528, 256>>>();
  finalize_kernel<<<1, 1>>>((float*)d_out);
}

// round 3
// speedup vs baseline: 2.9993x; 2.9993x over previous
#include <cuda_runtime.h>
#include <cuda_fp16.h>

// MMDLoss: hard-negative selection (argmax over 4x4 upsample candidates) + RBF MMD.
// x: (2,768,32,32) f32, y: (2,768,128,128) f32, output: scalar f32.
// Gram runs on legacy tensor-core path (ldmatrix + mma.sync m16n8k16 fp16/f32),
// since the harness emits compute_103 PTX (tcgen05 needs the 103a feature set).

#define GAMMA_F 0.00065f

constexpr int C_  = 768;
constexpr int N_  = 2048;
constexpr int NZ  = 4096;
constexpr int K_  = 768;

__device__ float  g_Z[NZ * K_];      // fp32 rows (X then Ysel)
__device__ __half g_Zh[NZ * K_];     // fp16 copy for MMA
__device__ float  g_sq[NZ];          // sqnorms of the fp16-rounded rows
__device__ float  g_D2P[N_ * 16 * 4];
__device__ int    g_idx[N_];
__device__ double g_acc[3];          // 0=xx strict-lower, 1=xy full, 2=yy strict-lower

// ---------------------------------------------------------------------------
// 1) Build X rows of Z (fp32)
// ---------------------------------------------------------------------------
__global__ void build_x_kernel(const float* __restrict__ x) {
  int n = blockIdx.x;
  int b = n >> 10, h1 = (n >> 5) & 31, w1 = n & 31;
  int base = (b * C_) * 1024 + h1 * 32 + w1;
#pragma unroll
  for (int k = 0; k < 3; ++k) {
    int c = threadIdx.x + 256 * k;
    g_Z[n * K_ + c] = x[base + c * 1024];
  }
}

// ---------------------------------------------------------------------------
// 2) Partial squared distances (coalesced y reads)
// ---------------------------------------------------------------------------
__global__ void d2_kernel(const float* __restrict__ y) {
  int chunk = blockIdx.x & 3;
  int r  = (blockIdx.x >> 2) & 3;
  int h1 = (blockIdx.x >> 4) & 31;
  int b  = blockIdx.x >> 9;
  int t  = threadIdx.x;
  int w1 = t >> 2;
  int n  = (b * 32 + h1) * 32 + w1;
  int c0 = chunk * 192;
  const float* yp = y + (size_t)(b * C_ + c0) * 16384 + (h1 * 4 + r) * 128 + t;
  const float* zp = g_Z + (size_t)n * K_ + c0;
  float a0 = 0.f, a1 = 0.f;
#pragma unroll 8
  for (int c = 0; c < 192; c += 2) {
    float d0 = zp[c]     - yp[(size_t)c * 16384];
    float d1 = zp[c + 1] - yp[(size_t)(c + 1) * 16384];
    a0 = fmaf(d0, d0, a0);
    a1 = fmaf(d1, d1, a1);
  }
  g_D2P[(n * 16 + (r * 4 + (t & 3))) * 4 + chunk] = a0 + a1;
}

// ---------------------------------------------------------------------------
// 3) Argmax (first-max tie rule)
// ---------------------------------------------------------------------------
__global__ void argmax_kernel() {
  int n = blockIdx.x * blockDim.x + threadIdx.x;
  if (n >= N_) return;
  const float* p = g_D2P + n * 64;
  float best = -1.f; int bi = 0;
#pragma unroll
  for (int j = 0; j < 16; ++j) {
    float d = (p[j * 4] + p[j * 4 + 1]) + (p[j * 4 + 2] + p[j * 4 + 3]);
    if (d > best) { best = d; bi = j; }
  }
  g_idx[n] = bi;
}

// ---------------------------------------------------------------------------
// 4) Gather selected y rows (fp32)
// ---------------------------------------------------------------------------
__global__ void gather_kernel(const float* __restrict__ y) {
  int n = blockIdx.x;
  int b = n >> 10, h1 = (n >> 5) & 31, w1 = n & 31;
  int j = g_idx[n];
  int h = h1 * 4 + (j >> 2), w = w1 * 4 + (j & 3);
  size_t base = (size_t)(b * C_) * 16384 + (size_t)h * 128 + w;
#pragma unroll
  for (int k = 0; k < 3; ++k) {
    int c = threadIdx.x + 256 * k;
    g_Z[(size_t)(N_ + n) * K_ + c] = y[base + (size_t)c * 16384];
  }
}

// ---------------------------------------------------------------------------
// 5) Convert to fp16 + sqnorm of the rounded values (consistency for d2)
// ---------------------------------------------------------------------------
__global__ void convert_kernel() {
  int i = blockIdx.x;
  const float* row = g_Z + (size_t)i * K_;
  __half* hrow = g_Zh + (size_t)i * K_;
  float s = 0.f;
#pragma unroll
  for (int k = 0; k < 3; ++k) {
    int c = threadIdx.x + 256 * k;
    __half h = __float2half_rn(row[c]);
    hrow[c] = h;
    float v = __half2float(h);
    s = fmaf(v, v, s);
  }
  for (int off = 16; off; off >>= 1) s += __shfl_down_sync(0xffffffffu, s, off);
  __shared__ float red[8];
  int lane = threadIdx.x & 31, wid = threadIdx.x >> 5;
  if (lane == 0) red[wid] = s;
  __syncthreads();
  if (threadIdx.x == 0) {
    float t = 0.f;
#pragma unroll
    for (int w = 0; w < 8; ++w) t += red[w];
    g_sq[i] = t;
  }
}

__global__ void zero_kernel() {
  if (threadIdx.x < 3) g_acc[threadIdx.x] = 0.0;
}

// ---------------------------------------------------------------------------
// 6) Tensor-core gram: 128x128 CTA tiles over lower triangle (528 CTAs).
//    fp16 inputs, fp32 accum, ldmatrix + mma.sync m16n8k16.
//    SMEM tile: 128 rows x 32 halfs (64B/row), XOR swizzle on 16B chunks.
// ---------------------------------------------------------------------------
__device__ __forceinline__ int swz(int row, int chunk) {
  return row * 64 + ((chunk ^ ((row >> 1) & 3)) << 4);
}
__device__ __forceinline__ unsigned smem_u32(const void* p) {
  unsigned a;
  asm("{ .reg .u64 t; cvta.to.shared.u64 t, %1; cvt.u32.u64 %0, t; }" : "=r"(a) : "l"(p));
  return a;
}
__device__ __forceinline__ void ldsm4(unsigned* r, unsigned addr) {
  asm volatile("ldmatrix.sync.aligned.m8n8.x4.shared.b16 {%0,%1,%2,%3}, [%4];"
               : "=r"(r[0]), "=r"(r[1]), "=r"(r[2]), "=r"(r[3]) : "r"(addr));
}
__device__ __forceinline__ void mma16816(float* c, const unsigned* a, const unsigned* b) {
  asm volatile("mma.sync.aligned.m16n8k16.row.col.f32.f16.f16.f32 "
               "{%0,%1,%2,%3}, {%4,%5,%6,%7}, {%8,%9}, {%0,%1,%2,%3};"
               : "+f"(c[0]), "+f"(c[1]), "+f"(c[2]), "+f"(c[3])
               : "r"(a[0]), "r"(a[1]), "r"(a[2]), "r"(a[3]), "r"(b[0]), "r"(b[1]));
}

constexpr int NCHUNK = 24;   // 768 / 32

__global__ void __launch_bounds__(256, 2) gram_mma_kernel() {
  __shared__ __align__(16) char As[2][8192];
  __shared__ __align__(16) char Bss[2][8192];
  __shared__ float red[8];

  int tid = threadIdx.x, lane = tid & 31, w = tid >> 5;
  int wm = w & 3, wn = w >> 2;

  int bid = blockIdx.x;
  int br = (int)((sqrtf(8.f * (float)bid + 1.f) - 1.f) * 0.5f);
  while ((br + 1) * (br + 2) / 2 <= bid) br++;
  while (br * (br + 1) / 2 > bid) br--;
  int bc = bid - br * (br + 1) / 2;
  bool diag = (br == bc);
  int i0 = br * 128, j0 = bc * 128;
  int cls = (br < 16) ? 0 : ((bc < 16) ? 1 : 2);

  // global load mapping: thread t -> row t>>1, 16 halfs starting at (t&1)*16
  int lrow = tid >> 1, lcol = (tid & 1) * 16, cb = (tid & 1) * 2;
  const __half* gA = g_Zh + (size_t)(i0 + lrow) * K_ + lcol;
  const __half* gB = g_Zh + (size_t)(j0 + lrow) * K_ + lcol;

  // ldmatrix per-lane addressing
  int a_row = wm * 32 + (lane & 7) + ((lane >> 3) & 1) * 8;
  int a_chv = (lane >> 4);            // +0/+1 chunk (k-lo / k-hi)
  int b_row = wn * 64 + (lane & 7) + (lane >> 4) * 8;
  int b_chv = (lane >> 3) & 1;

  float acc[2][8][4];
#pragma unroll
  for (int mt = 0; mt < 2; ++mt)
#pragma unroll
    for (int nt = 0; nt < 8; ++nt)
#pragma unroll
      for (int q = 0; q < 4; ++q) acc[mt][nt][q] = 0.f;

  const char* Bsrc0 = diag ? As[0] : Bss[0];
  const char* Bsrc1 = diag ? As[1] : Bss[1];

  // preload chunk 0
  {
    uint4 a0 = *(const uint4*)gA;
    uint4 a1 = *(const uint4*)(gA + 8);
    *(uint4*)(As[0] + swz(lrow, cb))     = a0;
    *(uint4*)(As[0] + swz(lrow, cb + 1)) = a1;
    if (!diag) {
      uint4 b0 = *(const uint4*)gB;
      uint4 b1 = *(const uint4*)(gB + 8);
      *(uint4*)(Bss[0] + swz(lrow, cb))     = b0;
      *(uint4*)(Bss[0] + swz(lrow, cb + 1)) = b1;
    }
  }
  __syncthreads();

  int buf = 0;
  for (int cn = 0; cn < NCHUNK; ++cn) {
    // prefetch next chunk into registers
    uint4 pa0, pa1, pb0, pb1;
    if (cn + 1 < NCHUNK) {
      const __half* ga = gA + (cn + 1) * 32;
      pa0 = *(const uint4*)ga;
      pa1 = *(const uint4*)(ga + 8);
      if (!diag) {
        const __half* gb = gB + (cn + 1) * 32;
        pb0 = *(const uint4*)gb;
        pb1 = *(const uint4*)(gb + 8);
      }
    }

    const char* at = As[buf];
    const char* bt = buf ? Bsrc1 : Bsrc0;
    unsigned abase = smem_u32(at), bbase = smem_u32(bt);
#pragma unroll
    for (int ks = 0; ks < 2; ++ks) {
      unsigned afr[2][4];
#pragma unroll
      for (int mt = 0; mt < 2; ++mt)
        ldsm4(afr[mt], abase + swz(a_row + mt * 16, ks * 2 + a_chv));
      unsigned bfr[8][2];
#pragma unroll
      for (int p = 0; p < 4; ++p) {
        unsigned r[4];
        ldsm4(r, bbase + swz(b_row + p * 16, ks * 2 + b_chv));
        bfr[2 * p][0] = r[0]; bfr[2 * p][1] = r[1];
        bfr[2 * p + 1][0] = r[2]; bfr[2 * p + 1][1] = r[3];
      }
#pragma unroll
      for (int mt = 0; mt < 2; ++mt)
#pragma unroll
        for (int nt = 0; nt < 8; ++nt)
          mma16816(acc[mt][nt], afr[mt], bfr[nt]);
    }

    if (cn + 1 < NCHUNK) {
      int nb = buf ^ 1;
      *(uint4*)(As[nb] + swz(lrow, cb))     = pa0;
      *(uint4*)(As[nb] + swz(lrow, cb + 1)) = pa1;
      if (!diag) {
        *(uint4*)(Bss[nb] + swz(lrow, cb))     = pb0;
        *(uint4*)(Bss[nb] + swz(lrow, cb + 1)) = pb1;
      }
    }
    __syncthreads();
    buf ^= 1;
  }

  // epilogue: dist -> exp -> masked accumulate (C frag layout of m16n8k16)
  int g = lane >> 2, qp = 2 * (lane & 3);
  float lsum = 0.f;
#pragma unroll
  for (int mt = 0; mt < 2; ++mt) {
    int ia = i0 + wm * 32 + mt * 16 + g;
    int ib = ia + 8;
    float sqa = g_sq[ia], sqb = g_sq[ib];
#pragma unroll
    for (int nt = 0; nt < 8; ++nt) {
      int jb0 = j0 + wn * 64 + nt * 8 + qp;
      float sj0 = g_sq[jb0], sj1 = g_sq[jb0 + 1];
      float d00 = fmaxf(sqa + sj0 - 2.f * acc[mt][nt][0], 0.f);
      float d01 = fmaxf(sqa + sj1 - 2.f * acc[mt][nt][1], 0.f);
      float d10 = fmaxf(sqb + sj0 - 2.f * acc[mt][nt][2], 0.f);
      float d11 = fmaxf(sqb + sj1 - 2.f * acc[mt][nt][3], 0.f);
      float e00 = __expf(-GAMMA_F * d00);
      float e01 = __expf(-GAMMA_F * d01);
      float e10 = __expf(-GAMMA_F * d10);
      float e11 = __expf(-GAMMA_F * d11);
      if (!diag) {
        lsum += (e00 + e01) + (e10 + e11);
      } else {
        if (jb0     < ia) lsum += e00;
        if (jb0 + 1 < ia) lsum += e01;
        if (jb0     < ib) lsum += e10;
        if (jb0 + 1 < ib) lsum += e11;
      }
    }
  }

  for (int off = 16; off; off >>= 1) lsum += __shfl_down_sync(0xffffffffu, lsum, off);
  if (lane == 0) red[w] = lsum;
  __syncthreads();
  if (tid == 0) {
    float s = 0.f;
#pragma unroll
    for (int k = 0; k < 8; ++k) s += red[k];
    atomicAdd(&g_acc[cls], (double)s);
  }
}

// ---------------------------------------------------------------------------
// 7) Final combine (diagonal of Kxx/Kyy added exactly: exp(0)=1)
// ---------------------------------------------------------------------------
__global__ void finalize_kernel(float* out) {
  double sxx = 2.0 * g_acc[0] + (double)N_;
  double syy = 2.0 * g_acc[2] + (double)N_;
  double sxy = g_acc[1];
  out[0] = (float)((sxx + syy - 2.0 * sxy) / ((double)N_ * (double)N_));
}

extern "C" void kernel_launch(void* const* d_in, const int* in_sizes, int n_in,
                              void* d_out, int out_size) {
  const float* x = (const float*)d_in[0];
  const float* y = (const float*)d_in[1];

  build_x_kernel<<<2048, 256>>>(x);
  d2_kernel<<<1024, 128>>>(y);
  argmax_kernel<<<8, 256>>>();
  gather_kernel<<<2048, 256>>>(y);
  convert_kernel<<<4096, 256>>>();
  zero_kernel<<<1, 32>>>();
  gram_mma_kernel<<<528, 256>>>();
  finalize_kernel<<<1, 1>>>((float*)d_out);
}

// round 4
// speedup vs baseline: 3.5988x; 1.1999x over previous
#include <cuda_runtime.h>
#include <cuda_fp16.h>

// MMDLoss: hard-negative selection + RBF MMD, sm_103a (compute_103 PTX -> no tcgen05).
// Gram on ldmatrix + mma.sync m16n8k16 fp16/f32 with cp.async 3-stage pipeline.

#define GAMMA_F 0.00065f

constexpr int C_  = 768;
constexpr int N_  = 2048;
constexpr int NZ  = 4096;
constexpr int K_  = 768;

__device__ float    g_Z[N_ * K_];      // fp32 X rows only (for d2)
__device__ __half   g_Zh[NZ * K_];     // fp16 rows: X then Ysel
__device__ float    g_sq[NZ];          // sqnorms of fp16-rounded rows
__device__ float    g_D2P[N_ * 16 * 8];// partial d2: [n][j(16)][chunk(8)]
__device__ double   g_acc[3];
__device__ unsigned g_cnt;

// ---------------------------------------------------------------------------
// 1) Transposed build of X rows: x(b,c,p) -> Z[b*1024+p][c], 32x32 SMEM tiles
// ---------------------------------------------------------------------------
__global__ void buildT_kernel(const float* __restrict__ x) {
  __shared__ float tile[32][33];
  int bid = blockIdx.x;
  int b = bid >= 768 ? 1 : 0;
  int rr = bid - b * 768;
  int cT = rr >> 5, pT = rr & 31;           // 24 x 32
  int c0 = cT * 32, p0 = pT * 32;
  int t = threadIdx.x;
  int ci = t >> 5, pi = t & 31;
#pragma unroll
  for (int q = 0; q < 4; ++q)
    tile[ci * 4 + q][pi] = x[(size_t)(b * C_ + c0 + ci * 4 + q) * 1024 + p0 + pi];
  __syncthreads();
  int p2 = t >> 5, c2 = t & 31;
#pragma unroll
  for (int q = 0; q < 4; ++q)
    g_Z[(size_t)(b * 1024 + p0 + p2 * 4 + q) * K_ + c0 + c2] = tile[c2][p2 * 4 + q];
}

// ---------------------------------------------------------------------------
// 2) Convert X rows to fp16 + sqnorm; zero accumulators (block 0)
// ---------------------------------------------------------------------------
__global__ void convx_kernel() {
  int i = blockIdx.x, t = threadIdx.x;
  if (i == 0) {
    if (t < 3) g_acc[t] = 0.0;
    if (t == 3) g_cnt = 0u;
  }
  const float* row = g_Z + (size_t)i * K_;
  __half* hrow = g_Zh + (size_t)i * K_;
  float s = 0.f;
#pragma unroll
  for (int k = 0; k < 3; ++k) {
    int c = t + 256 * k;
    __half h = __float2half_rn(row[c]);
    hrow[c] = h;
    float v = __half2float(h);
    s = fmaf(v, v, s);
  }
  for (int off = 16; off; off >>= 1) s += __shfl_down_sync(0xffffffffu, s, off);
  __shared__ float red[8];
  int lane = t & 31, w = t >> 5;
  if (lane == 0) red[w] = s;
  __syncthreads();
  if (t == 0) {
    float tt = 0.f;
#pragma unroll
    for (int k = 0; k < 8; ++k) tt += red[k];
    g_sq[i] = tt;
  }
}

// ---------------------------------------------------------------------------
// 3) Partial d2: block=(b,h1,chunk of 96 c), thread=(r,w1). float4 along w
//    covers all 4 jw candidates per load. X rows staged in SMEM (pad 97).
// ---------------------------------------------------------------------------
__global__ void d2_kernel(const float* __restrict__ y) {
  __shared__ float Zs[32][97];
  int bid = blockIdx.x;
  int chunk = bid & 7, h1 = (bid >> 3) & 31, b = bid >> 8;
  int t = threadIdx.x, r = t >> 5, w1 = t & 31;
  int n0 = (b * 32 + h1) * 32;
  int c0 = chunk * 96;
#pragma unroll
  for (int p = 0; p < 8; ++p) {
    int row = p * 4 + r;
#pragma unroll
    for (int g = 0; g < 3; ++g) {
      int c = w1 + 32 * g;
      Zs[row][c] = g_Z[(size_t)(n0 + row) * K_ + c0 + c];
    }
  }
  __syncthreads();
  const float* yp = y + (size_t)(b * C_ + c0) * 16384 + (h1 * 4 + r) * 128 + w1 * 4;
  float a0 = 0.f, a1 = 0.f, a2 = 0.f, a3 = 0.f;
#pragma unroll 4
  for (int c = 0; c < 96; ++c) {
    float4 v = *(const float4*)(yp + (size_t)c * 16384);
    float z = Zs[w1][c];
    float d0 = z - v.x, d1 = z - v.y, d2 = z - v.z, d3 = z - v.w;
    a0 = fmaf(d0, d0, a0); a1 = fmaf(d1, d1, a1);
    a2 = fmaf(d2, d2, a2); a3 = fmaf(d3, d3, a3);
  }
  float* dst = g_D2P + (size_t)(n0 + w1) * 128 + r * 32 + chunk;
  dst[0]  = a0;
  dst[8]  = a1;
  dst[16] = a2;
  dst[24] = a3;
}

// ---------------------------------------------------------------------------
// 4) Fused argmax (first-max tie rule) + gather -> fp16 + sqnorm
// ---------------------------------------------------------------------------
__global__ void gather_kernel(const float* __restrict__ y) {
  __shared__ int jsh;
  __shared__ float red[8];
  int n = blockIdx.x, t = threadIdx.x, lane = t & 31, w = t >> 5;
  if (w == 0) {
    int j = lane & 15;
    const float* p = g_D2P + (size_t)n * 128 + j * 8;
    float4 u = *(const float4*)p;
    float4 v = *(const float4*)(p + 4);
    float d = ((u.x + u.y) + (u.z + u.w)) + ((v.x + v.y) + (v.z + v.w));
#pragma unroll
    for (int off = 8; off; off >>= 1) {
      float od = __shfl_down_sync(0xffffffffu, d, off);
      int   oj = __shfl_down_sync(0xffffffffu, j, off);
      if (od > d) { d = od; j = oj; }   // tie keeps lower-j subtree = first max
    }
    if (lane == 0) jsh = j;
  }
  __syncthreads();
  int j = jsh;
  int b = n >> 10, h1 = (n >> 5) & 31, w1 = n & 31;
  int h = h1 * 4 + (j >> 2), wq = w1 * 4 + (j & 3);
  const float* yb = y + (size_t)(b * C_) * 16384 + (size_t)h * 128 + wq;
  __half* hrow = g_Zh + (size_t)(N_ + n) * K_;
  float s = 0.f;
#pragma unroll
  for (int k = 0; k < 3; ++k) {
    int c = t + 256 * k;
    __half hv = __float2half_rn(yb[(size_t)c * 16384]);
    hrow[c] = hv;
    float v = __half2float(hv);
    s = fmaf(v, v, s);
  }
  for (int off = 16; off; off >>= 1) s += __shfl_down_sync(0xffffffffu, s, off);
  if (lane == 0) red[w] = s;
  __syncthreads();
  if (t == 0) {
    float tt = 0.f;
#pragma unroll
    for (int k = 0; k < 8; ++k) tt += red[k];
    g_sq[N_ + n] = tt;
  }
}

// ---------------------------------------------------------------------------
// 5) Tensor-core gram, cp.async 3-stage pipeline, fused epilogue + finalize
// ---------------------------------------------------------------------------
__device__ __forceinline__ int swz(int row, int chunk) {
  return row * 64 + ((chunk ^ ((row >> 1) & 3)) << 4);
}
__device__ __forceinline__ unsigned smem_u32(const void* p) {
  unsigned a;
  asm("{ .reg .u64 t; cvta.to.shared.u64 t, %1; cvt.u32.u64 %0, t; }" : "=r"(a) : "l"(p));
  return a;
}
__device__ __forceinline__ void cpa16(unsigned dst, const void* src) {
  asm volatile("cp.async.cg.shared.global [%0], [%1], 16;" :: "r"(dst), "l"(src) : "memory");
}
__device__ __forceinline__ void ldsm4(unsigned* r, unsigned addr) {
  asm volatile("ldmatrix.sync.aligned.m8n8.x4.shared.b16 {%0,%1,%2,%3}, [%4];"
               : "=r"(r[0]), "=r"(r[1]), "=r"(r[2]), "=r"(r[3]) : "r"(addr));
}
__device__ __forceinline__ void mma16816(float* c, const unsigned* a, const unsigned* b) {
  asm volatile("mma.sync.aligned.m16n8k16.row.col.f32.f16.f16.f32 "
               "{%0,%1,%2,%3}, {%4,%5,%6,%7}, {%8,%9}, {%0,%1,%2,%3};"
               : "+f"(c[0]), "+f"(c[1]), "+f"(c[2]), "+f"(c[3])
               : "r"(a[0]), "r"(a[1]), "r"(a[2]), "r"(a[3]), "r"(b[0]), "r"(b[1]));
}

constexpr int NCHUNK = 24;   // 768 / 32

__global__ void __launch_bounds__(256, 2) gram_mma_kernel(float* __restrict__ out) {
  __shared__ __align__(16) char As[3][8192];
  __shared__ __align__(16) char Bs2[3][8192];
  __shared__ float red[8];

  int tid = threadIdx.x, lane = tid & 31, w = tid >> 5;
  int wm = w & 3, wn = w >> 2;

  int bid = blockIdx.x;
  int br = (int)((sqrtf(8.f * (float)bid + 1.f) - 1.f) * 0.5f);
  while ((br + 1) * (br + 2) / 2 <= bid) br++;
  while (br * (br + 1) / 2 > bid) br--;
  int bc = bid - br * (br + 1) / 2;
  bool diag = (br == bc);
  int i0 = br * 128, j0 = bc * 128;
  int cls = (br < 16) ? 0 : ((bc < 16) ? 1 : 2);

  // cp.async mapping: thread -> row tid>>1, 32B half-row tid&1
  int lrow = tid >> 1, hb = tid & 1, cb = hb * 2;
  const __half* gA = g_Zh + (size_t)(i0 + lrow) * K_ + hb * 16;
  const __half* gB = g_Zh + (size_t)(j0 + lrow) * K_ + hb * 16;

  unsigned aAddr[3], bAddr[3];
#pragma unroll
  for (int s3 = 0; s3 < 3; ++s3) {
    aAddr[s3] = smem_u32(As[s3]);
    bAddr[s3] = smem_u32(Bs2[s3]);
  }

  auto issue = [&](int cn) {
    int bf = cn % 3;
    const __half* sa = gA + cn * 32;
    cpa16(aAddr[bf] + swz(lrow, cb),     sa);
    cpa16(aAddr[bf] + swz(lrow, cb + 1), sa + 8);
    if (!diag) {
      const __half* sb = gB + cn * 32;
      cpa16(bAddr[bf] + swz(lrow, cb),     sb);
      cpa16(bAddr[bf] + swz(lrow, cb + 1), sb + 8);
    }
    asm volatile("cp.async.commit_group;" ::: "memory");
  };

  // ldmatrix per-lane addressing (validated in R3)
  int a_row = wm * 32 + (lane & 7) + ((lane >> 3) & 1) * 8;
  int a_chv = lane >> 4;
  int b_row = wn * 64 + (lane & 7) + (lane >> 4) * 8;
  int b_chv = (lane >> 3) & 1;

  float acc[2][8][4];
#pragma unroll
  for (int mt = 0; mt < 2; ++mt)
#pragma unroll
    for (int nt = 0; nt < 8; ++nt)
#pragma unroll
      for (int q = 0; q < 4; ++q) acc[mt][nt][q] = 0.f;

  issue(0);
  issue(1);

#pragma unroll 1
  for (int cn = 0; cn < NCHUNK; ++cn) {
    if (cn < NCHUNK - 2) asm volatile("cp.async.wait_group 1;" ::: "memory");
    else                 asm volatile("cp.async.wait_group 0;" ::: "memory");
    __syncthreads();                 // chunk cn visible; compute cn-1 done everywhere
    if (cn + 2 < NCHUNK) issue(cn + 2);

    int bf = cn % 3;
    unsigned abase = aAddr[bf];
    unsigned bbase = diag ? aAddr[bf] : bAddr[bf];
#pragma unroll
    for (int ks = 0; ks < 2; ++ks) {
      unsigned afr[2][4];
#pragma unroll
      for (int mt = 0; mt < 2; ++mt)
        ldsm4(afr[mt], abase + swz(a_row + mt * 16, ks * 2 + a_chv));
      unsigned bfr[8][2];
#pragma unroll
      for (int p = 0; p < 4; ++p) {
        unsigned r4[4];
        ldsm4(r4, bbase + swz(b_row + p * 16, ks * 2 + b_chv));
        bfr[2 * p][0] = r4[0];     bfr[2 * p][1] = r4[1];
        bfr[2 * p + 1][0] = r4[2]; bfr[2 * p + 1][1] = r4[3];
      }
#pragma unroll
      for (int mt = 0; mt < 2; ++mt)
#pragma unroll
        for (int nt = 0; nt < 8; ++nt)
          mma16816(acc[mt][nt], afr[mt], bfr[nt]);
    }
  }

  // epilogue: dist -> exp -> masked accumulate
  int g = lane >> 2, qp = 2 * (lane & 3);
  float lsum = 0.f;
#pragma unroll
  for (int mt = 0; mt < 2; ++mt) {
    int ia = i0 + wm * 32 + mt * 16 + g;
    int ib = ia + 8;
    float sqa = g_sq[ia], sqb = g_sq[ib];
#pragma unroll
    for (int nt = 0; nt < 8; ++nt) {
      int jb0 = j0 + wn * 64 + nt * 8 + qp;
      float sj0 = g_sq[jb0], sj1 = g_sq[jb0 + 1];
      float d00 = fmaxf(sqa + sj0 - 2.f * acc[mt][nt][0], 0.f);
      float d01 = fmaxf(sqa + sj1 - 2.f * acc[mt][nt][1], 0.f);
      float d10 = fmaxf(sqb + sj0 - 2.f * acc[mt][nt][2], 0.f);
      float d11 = fmaxf(sqb + sj1 - 2.f * acc[mt][nt][3], 0.f);
      float e00 = __expf(-GAMMA_F * d00);
      float e01 = __expf(-GAMMA_F * d01);
      float e10 = __expf(-GAMMA_F * d10);
      float e11 = __expf(-GAMMA_F * d11);
      if (!diag) {
        lsum += (e00 + e01) + (e10 + e11);
      } else {
        if (jb0     < ia) lsum += e00;
        if (jb0 + 1 < ia) lsum += e01;
        if (jb0     < ib) lsum += e10;
        if (jb0 + 1 < ib) lsum += e11;
      }
    }
  }

  for (int off = 16; off; off >>= 1) lsum += __shfl_down_sync(0xffffffffu, lsum, off);
  if (lane == 0) red[w] = lsum;
  __syncthreads();
  if (tid == 0) {
    float s = 0.f;
#pragma unroll
    for (int k = 0; k < 8; ++k) s += red[k];
    atomicAdd(&g_acc[cls], (double)s);
    __threadfence();
    unsigned old = atomicAdd(&g_cnt, 1u);
    if (old == 527u) {               // last CTA finalizes
      volatile double* a = g_acc;
      double sxx = 2.0 * a[0] + (double)N_;
      double syy = 2.0 * a[2] + (double)N_;
      double sxy = a[1];
      out[0] = (float)((sxx + syy - 2.0 * sxy) / ((double)N_ * (double)N_));
    }
  }
}

extern "C" void kernel_launch(void* const* d_in, const int* in_sizes, int n_in,
                              void* d_out, int out_size) {
  const float* x = (const float*)d_in[0];
  const float* y = (const float*)d_in[1];

  buildT_kernel<<<1536, 256>>>(x);
  convx_kernel<<<2048, 256>>>();
  d2_kernel<<<512, 128>>>(y);
  gather_kernel<<<2048, 256>>>(y);
  gram_mma_kernel<<<528, 256>>>((float*)d_out);
}